// round 11
// baseline (speedup 1.0000x reference)
#include <cuda_runtime.h>
#include <cuda_bf16.h>
#include <cstdint>

#define B_   16
#define L_   2048
#define H_   512
#define N_   64

// ---------------- fused-kernel dynamic smem layout (byte offsets) ------------
#define oW    0          // W half [64][72] bf16 hi+lo = 18432 B
#define oA2T  18432      // A2 half: 6 tiles [64][40] bf16 = 30720 B
#define oU    49152      // u: 2 bufs x ([32][72] hi + lo = 9216) = 18432 B
#define oD1   67584      // D1 [64][36] fp32 = 9216 B (overlaid by D2 [64][33])
#define oX    76800      // X: xrH,xrL,xiH,xiL [32][40] bf16 = 10240 B
#define SMEM_TOTAL 87040

// ---------------- scratch (__device__ globals) --------------------------------
__device__ __align__(16) __nv_bfloat16 gW  [H_ * 18432];   // per h: 2 halves x (hi 4608 | lo 4608)
__device__ __align__(16) __nv_bfloat16 gA2 [H_ * 30720];   // per h: 2 halves x 6 tiles [64][40]
__device__ __align__(16) float2 d_AbC[H_ * N_];             // Ab^C
__device__ __align__(16) float  d_ut [B_ * H_ * L_];        // u transposed (B,H,L)
__device__ __align__(16) float  d_yt0[B_ * H_ * L_];        // partial y (half 0)
__device__ __align__(16) float  d_yt1[B_ * H_ * L_];        // partial y (half 1)

__device__ __forceinline__ float2 cmul(float2 a, float2 b) {
    return make_float2(a.x * b.x - a.y * b.y, a.x * b.y + a.y * b.x);
}

// ---------------- PTX helpers (compute_80+; valid on plain sm_103) -----------
__device__ __forceinline__ uint32_t smem_to_u32(const void* p) {
    uint32_t a;
    asm("{ .reg .u64 t; cvta.to.shared.u64 t, %1; cvt.u32.u64 %0, t; }" : "=r"(a) : "l"(p));
    return a;
}
__device__ __forceinline__ void ldm_x4(uint32_t* r, uint32_t addr) {
    asm volatile("ldmatrix.sync.aligned.m8n8.x4.shared.b16 {%0,%1,%2,%3}, [%4];"
                 : "=r"(r[0]), "=r"(r[1]), "=r"(r[2]), "=r"(r[3]) : "r"(addr));
}
__device__ __forceinline__ void ldm_x2(uint32_t* r, uint32_t addr) {
    asm volatile("ldmatrix.sync.aligned.m8n8.x2.shared.b16 {%0,%1}, [%2];"
                 : "=r"(r[0]), "=r"(r[1]) : "r"(addr));
}
__device__ __forceinline__ void mma16816(float* d, const uint32_t* a, const uint32_t* b) {
    asm volatile("mma.sync.aligned.m16n8k16.row.col.f32.bf16.bf16.f32 "
                 "{%0,%1,%2,%3}, {%4,%5,%6,%7}, {%8,%9}, {%0,%1,%2,%3};"
                 : "+f"(d[0]), "+f"(d[1]), "+f"(d[2]), "+f"(d[3])
                 : "r"(a[0]), "r"(a[1]), "r"(a[2]), "r"(a[3]), "r"(b[0]), "r"(b[1]));
}

// split fp32 into bf16 hi/lo
__device__ __forceinline__ void put2(__nv_bfloat16* th, __nv_bfloat16* tl, int idx, float v) {
    __nv_bfloat16 hv = __float2bfloat16(v);
    th[idx] = hv;
    tl[idx] = __float2bfloat16(v - __bfloat162float(hv));
}

// ---------------- precompute: discretization + half-split operators ----------
__global__ void precompute_kernel(const float* __restrict__ Lr,
                                  const float* __restrict__ Li,
                                  const float* __restrict__ Br,
                                  const float* __restrict__ Bi,
                                  const float* __restrict__ Cr,
                                  const float* __restrict__ Ci,
                                  const float* __restrict__ logdt,
                                  const float* __restrict__ Din) {
    int h = blockIdx.x;
    int n = threadIdx.x;             // 64 threads; half = n>>5, nl = n&31
    int lane = n & 31, wid = n >> 5;
    int half = n >> 5, nl = n & 31;

    float dt  = expf(logdt[h]);
    float lr  = Lr[n], li = Li[n];
    float er = expf(dt * lr);
    float s, c;
    sincosf(dt * li, &s, &c);
    float2 Ab = make_float2(er * c, er * s);

    float dr = lr + 1e-8f, di = li;
    float inv = 1.0f / (dr * dr + di * di);
    float2 Am1 = make_float2(Ab.x - 1.0f, Ab.y);
    float2 Bc  = make_float2(Br[h * N_ + n], Bi[h * N_ + n]);
    float2 num = cmul(Bc, Am1);
    float2 Bb  = make_float2((num.x * dr + num.y * di) * inv,
                             (num.y * dr - num.x * di) * inv);
    float2 Cc  = make_float2(Cr[h * N_ + n], Ci[h * N_ + n]);
    float2 CB  = cmul(Cc, Bb);

    __shared__ float sKpart[64][2];
    __shared__ float sKd[64];

    __nv_bfloat16* WH  = gW + (size_t)h * 18432 + half * 9216;   // [64][72]
    __nv_bfloat16* WL  = WH + 4608;
    __nv_bfloat16* A2b = gA2 + (size_t)h * 30720 + half * 15360; // 6 x [64][40]
    __nv_bfloat16* s0H = A2b,         * s0L = A2b + 2560;
    __nv_bfloat16* s1H = A2b + 5120,  * s1L = A2b + 7680;
    __nv_bfloat16* s2H = A2b + 10240, * s2L = A2b + 12800;

    float2 p = make_float2(1.0f, 0.0f);              // Ab^e
    for (int e = 0; e < 64; e++) {
        float2 w = cmul(p, Bb);                      // = Ab^{63-j} Bb at j = 63-e
        int j = 63 - e;
        put2(WH, WL, nl * 72 + j, w.x);              // real row nl
        put2(WH, WL, (32 + nl) * 72 + j, w.y);       // imag row 32+nl
        float kv = CB.x * p.x - CB.y * p.y;          // K[e] partial (this n)
        #pragma unroll
        for (int off = 16; off; off >>= 1) kv += __shfl_xor_sync(0xffffffffu, kv, off);
        if (lane == 0) sKpart[e][wid] = kv;
        p = cmul(p, Ab);                             // Ab^{e+1}
        float2 m = cmul(Cc, p);                      // M[i=e][n]
        put2(s0H, s0L, e * 40 + nl, m.x);            // seg0: Mr column nl
        put2(s1H, s1L, e * 40 + nl, -m.y);           // seg1: -Mi
    }
    d_AbC[h * N_ + n] = p;                           // Ab^C
    __syncthreads();
    sKd[n] = sKpart[n][0] + sKpart[n][1];            // K[d = n]
    __syncthreads();

    float Dh = Din[h];
    for (int i = 0; i < 64; i++) {                   // seg2: Toeplitz col j = n (+D diag)
        float v = (i > n) ? sKd[i - n] : (i == n ? sKd[0] + Dh : 0.0f);
        put2(s2H, s2L, i * 40 + nl, v);
    }
}

// ---------------- transposes (float4 both gmem sides) --------------------------
__global__ void transpose_BLH_to_BHL(const float* __restrict__ in, float* __restrict__ out) {
    __shared__ float tile[32][36];
    int b = blockIdx.z;
    int h0 = blockIdx.x * 32, l0 = blockIdx.y * 32;
    int t = threadIdx.x;                 // 256
    {
        int l = t >> 3, hq = t & 7;
        float4 v = *(const float4*)(in + ((size_t)b * L_ + l0 + l) * H_ + h0 + hq * 4);
        tile[hq * 4 + 0][l] = v.x;
        tile[hq * 4 + 1][l] = v.y;
        tile[hq * 4 + 2][l] = v.z;
        tile[hq * 4 + 3][l] = v.w;
    }
    __syncthreads();
    {
        int hh = t >> 3, lq = t & 7;
        float4 w = *(const float4*)&tile[hh][lq * 4];
        *(float4*)(out + ((size_t)b * H_ + h0 + hh) * L_ + l0 + lq * 4) = w;
    }
}

// final transpose: sums the two half partials
__global__ void transpose_sum_BHL_to_BLH(const float* __restrict__ in0,
                                         const float* __restrict__ in1,
                                         float* __restrict__ out) {
    __shared__ float tile[32][36];
    int b = blockIdx.z;
    int l0 = blockIdx.x * 32, h0 = blockIdx.y * 32;
    int t = threadIdx.x;                 // 256
    {
        int hh = t >> 3, lq = t & 7;
        size_t off = ((size_t)b * H_ + h0 + hh) * L_ + l0 + lq * 4;
        float4 v = *(const float4*)(in0 + off);
        float4 v2 = *(const float4*)(in1 + off);
        tile[lq * 4 + 0][hh] = v.x + v2.x;
        tile[lq * 4 + 1][hh] = v.y + v2.y;
        tile[lq * 4 + 2][hh] = v.z + v2.z;
        tile[lq * 4 + 3][hh] = v.w + v2.w;
    }
    __syncthreads();
    {
        int l = t >> 3, hq = t & 7;
        float4 w = *(const float4*)&tile[l][hq * 4];
        *(float4*)(out + ((size_t)b * L_ + l0 + l) * H_ + h0 + hq * 4) = w;
    }
}

// ---------------- u staging helper (256 threads, 2 float4 each) ---------------
__device__ __forceinline__ void stage_u(char* smc, const float* __restrict__ up,
                                        int buf, int tid) {
    __nv_bfloat16* uh = (__nv_bfloat16*)(smc + oU + buf * 9216);
    __nv_bfloat16* ul = uh + 2304;
    #pragma unroll
    for (int r = 0; r < 2; r++) {
        int f = r * 256 + tid;
        float4 v = ((const float4*)up)[f];
        int idx = (f >> 4) * 72 + (f & 15) * 4;
        __nv_bfloat16 h0 = __float2bfloat16(v.x), h1 = __float2bfloat16(v.y);
        __nv_bfloat16 h2 = __float2bfloat16(v.z), h3 = __float2bfloat16(v.w);
        __nv_bfloat162 p0; p0.x = h0; p0.y = h1;
        __nv_bfloat162 p1; p1.x = h2; p1.y = h3;
        *(__nv_bfloat162*)(uh + idx)     = p0;
        *(__nv_bfloat162*)(uh + idx + 2) = p1;
        __nv_bfloat162 q0, q1;
        q0.x = __float2bfloat16(v.x - __bfloat162float(h0));
        q0.y = __float2bfloat16(v.y - __bfloat162float(h1));
        q1.x = __float2bfloat16(v.z - __bfloat162float(h2));
        q1.y = __float2bfloat16(v.w - __bfloat162float(h3));
        *(__nv_bfloat162*)(ul + idx)     = q0;
        *(__nv_bfloat162*)(ul + idx + 2) = q1;
    }
}

// ---------------- fused HMMA kernel: half-state blocks, 2 blocks/SM -----------
extern __shared__ char smc[];
__global__ __launch_bounds__(256, 2) void fused_kernel() {
    int h    = blockIdx.y;
    int half = blockIdx.x >> 1;
    int b0   = (blockIdx.x & 1) * 8;
    int tid  = threadIdx.x;
    int w    = tid >> 5, lane = tid & 31;
    int mq   = w & 3, nh = w >> 2;

    uint32_t sb = smem_to_u32(smc);

    // ---- stage operators: W half 18432 B + A2 half 30720 B
    {
        const float4* s = (const float4*)(gW + (size_t)h * 18432 + half * 9216);
        float4* d = (float4*)(smc + oW);
        for (int i = tid; i < 1152; i += 256) d[i] = s[i];
        s = (const float4*)(gA2 + (size_t)h * 30720 + half * 15360);
        d = (float4*)(smc + oA2T);
        for (int i = tid; i < 1920; i += 256) d[i] = s[i];
    }
    stage_u(smc, d_ut + ((size_t)b0 * H_ + h) * L_, 0, tid);

    // scan constants: nl = tid>>3 (0..31), q = tid&7
    int nl = tid >> 3, sq = tid & 7;
    float2 a1  = d_AbC[h * 64 + half * 32 + nl];
    float2 a2c = cmul(a1, a1);
    float2 a3c = cmul(a2c, a1);
    float2 a4c = cmul(a2c, a2c);
    float2 a8c = cmul(a4c, a4c);
    float2 a16c = cmul(a8c, a8c);
    __syncthreads();

    uint32_t laneA72 = (uint32_t)(((lane & 15) * 72 + (lane >> 4) * 8) * 2);
    uint32_t laneB72 = (uint32_t)(((lane & 7) * 72 + ((lane >> 3) & 1) * 8) * 2);
    uint32_t laneA40 = (uint32_t)(((lane & 15) * 40 + (lane >> 4) * 8) * 2);
    uint32_t laneB40 = (uint32_t)(((lane & 7) * 40 + ((lane >> 3) & 1) * 8) * 2);

    // ---- cache A2 half frags: 6 k-chunks x (hi, lo) = 48 regs
    uint32_t a2H[6][4], a2L[6][4];
    #pragma unroll
    for (int kc = 0; kc < 6; kc++) {
        int sg = kc >> 1, kt = kc & 1;
        uint32_t base = sb + oA2T + (uint32_t)(sg * 10240 + mq * 1280 + kt * 32) + laneA40;
        ldm_x4(a2H[kc], base);
        ldm_x4(a2L[kc], base + 5120);
    }

    uint32_t wHb = sb + oW + (uint32_t)(mq * 16 * 144) + laneA72;
    uint32_t wLb = wHb + 9216;
    float* sD1f = (float*)(smc + oD1);
    __nv_bfloat16* xrH = (__nv_bfloat16*)(smc + oX);
    __nv_bfloat16* xrL = xrH + 1280;
    __nv_bfloat16* xiH = xrH + 2560;
    __nv_bfloat16* xiL = xrH + 3840;
    float* ypbase = half ? d_yt1 : d_yt0;
    int gid = lane >> 2, tq = lane & 3;

    for (int it = 0; it < 8; it++) {
        int buf = it & 1;
        uint32_t uhB = sb + oU + (uint32_t)(buf * 9216) + laneB72;
        uint32_t ulB = uhB + 4608;

        // ---- P1: MMA1  D1[64,32] = Whalf[64,64] @ u[32,64]^T
        {
            float acc[2][4];
            #pragma unroll
            for (int nt = 0; nt < 2; nt++)
                #pragma unroll
                for (int i = 0; i < 4; i++) acc[nt][i] = 0.f;
            #pragma unroll
            for (int kt = 0; kt < 4; kt++) {
                uint32_t ko = kt * 32;
                uint32_t aH[4], aL[4];
                ldm_x4(aH, wHb + ko);
                ldm_x4(aL, wLb + ko);
                #pragma unroll
                for (int nt = 0; nt < 2; nt++) {
                    uint32_t bo = (uint32_t)((nh * 2 + nt) * 1152) + ko;
                    uint32_t bh[2], bl[2];
                    ldm_x2(bh, uhB + bo);
                    ldm_x2(bl, ulB + bo);
                    mma16816(acc[nt], aH, bh);
                    mma16816(acc[nt], aH, bl);
                    mma16816(acc[nt], aL, bh);
                }
            }
            #pragma unroll
            for (int nt = 0; nt < 2; nt++) {
                int c0 = nh * 16 + nt * 8 + tq * 2;
                int r0 = mq * 16 + gid;
                sD1f[r0 * 36 + c0]           = acc[nt][0];
                sD1f[r0 * 36 + c0 + 1]       = acc[nt][1];
                sD1f[(r0 + 8) * 36 + c0]     = acc[nt][2];
                sD1f[(r0 + 8) * 36 + c0 + 1] = acc[nt][3];
            }
        }
        __syncthreads();

        // ---- P2: scan (shuffle) + emit X; stage next u
        {
            float4 gr4 = *(const float4*)(sD1f + nl * 36 + sq * 4);
            float4 gi4 = *(const float4*)(sD1f + (32 + nl) * 36 + sq * 4);
            float h0r = gr4.x, h0i = gi4.x;
            float h1r = a1.x * h0r - a1.y * h0i + gr4.y;
            float h1i = a1.x * h0i + a1.y * h0r + gi4.y;
            float h2r = a1.x * h1r - a1.y * h1i + gr4.z;
            float h2i = a1.x * h1i + a1.y * h1r + gi4.z;
            float Sr  = a1.x * h2r - a1.y * h2i + gr4.w;
            float Si  = a1.x * h2i + a1.y * h2r + gi4.w;
            float tr, ti;
            tr = __shfl_up_sync(0xffffffffu, Sr, 1, 8);
            ti = __shfl_up_sync(0xffffffffu, Si, 1, 8);
            if (sq >= 1) { Sr += a4c.x * tr - a4c.y * ti;  Si += a4c.x * ti + a4c.y * tr; }
            tr = __shfl_up_sync(0xffffffffu, Sr, 2, 8);
            ti = __shfl_up_sync(0xffffffffu, Si, 2, 8);
            if (sq >= 2) { Sr += a8c.x * tr - a8c.y * ti;  Si += a8c.x * ti + a8c.y * tr; }
            tr = __shfl_up_sync(0xffffffffu, Sr, 4, 8);
            ti = __shfl_up_sync(0xffffffffu, Si, 4, 8);
            if (sq >= 4) { Sr += a16c.x * tr - a16c.y * ti; Si += a16c.x * ti + a16c.y * tr; }
            float X0r = __shfl_up_sync(0xffffffffu, Sr, 1, 8);
            float X0i = __shfl_up_sync(0xffffffffu, Si, 1, 8);
            if (sq == 0) { X0r = 0.f; X0i = 0.f; }

            int idx = (sq * 4) * 40 + nl;
            put2(xrH, xrL, idx, X0r);
            put2(xiH, xiL, idx, X0i);
            float pr = a1.x * X0r - a1.y * X0i + h0r;
            float pi = a1.x * X0i + a1.y * X0r + h0i;
            put2(xrH, xrL, idx + 40, pr);
            put2(xiH, xiL, idx + 40, pi);
            pr = a2c.x * X0r - a2c.y * X0i + h1r;
            pi = a2c.x * X0i + a2c.y * X0r + h1i;
            put2(xrH, xrL, idx + 80, pr);
            put2(xiH, xiL, idx + 80, pi);
            pr = a3c.x * X0r - a3c.y * X0i + h2r;
            pi = a3c.x * X0i + a3c.y * X0r + h2i;
            put2(xrH, xrL, idx + 120, pr);
            put2(xiH, xiL, idx + 120, pi);
        }
        if (it < 7)
            stage_u(smc, d_ut + ((size_t)(b0 + it + 1) * H_ + h) * L_, buf ^ 1, tid);
        __syncthreads();

        // ---- P3: MMA2  D2[64,32] = A2half[64,96] @ [xr|xi|u_half]^T
        {
            float acc[2][4];
            #pragma unroll
            for (int nt = 0; nt < 2; nt++)
                #pragma unroll
                for (int i = 0; i < 4; i++) acc[nt][i] = 0.f;
            #pragma unroll
            for (int kc = 0; kc < 6; kc++) {
                int sg = kc >> 1, kt = kc & 1;
                uint32_t bH, bL, nts;
                if (sg < 2) {
                    bH = sb + oX + (uint32_t)(sg * 5120 + kt * 32) + laneB40;
                    bL = bH + 2560;
                    nts = 640;
                } else {
                    bH = sb + oU + (uint32_t)(buf * 9216 + (half * 32 + kt * 16) * 2) + laneB72;
                    bL = bH + 4608;
                    nts = 1152;
                }
                #pragma unroll
                for (int nt = 0; nt < 2; nt++) {
                    uint32_t bo = (uint32_t)((nh * 2 + nt)) * nts;
                    uint32_t bh[2], bl[2];
                    ldm_x2(bh, bH + bo);
                    ldm_x2(bl, bL + bo);
                    mma16816(acc[nt], a2H[kc], bh);
                    mma16816(acc[nt], a2H[kc], bl);
                    mma16816(acc[nt], a2L[kc], bh);
                }
            }
            #pragma unroll
            for (int nt = 0; nt < 2; nt++) {
                int c0 = nh * 16 + nt * 8 + tq * 2;
                int i0 = mq * 16 + gid;
                sD1f[i0 * 33 + c0]           = acc[nt][0];
                sD1f[i0 * 33 + c0 + 1]       = acc[nt][1];
                sD1f[(i0 + 8) * 33 + c0]     = acc[nt][2];
                sD1f[(i0 + 8) * 33 + c0 + 1] = acc[nt][3];
            }
        }
        __syncthreads();

        // ---- P4: store partial y
        {
            float* yp = ypbase + ((size_t)(b0 + it) * H_ + h) * L_;
            #pragma unroll
            for (int rep = 0; rep < 2; rep++) {
                int idx = rep * 256 + tid;
                int c = idx >> 4, i0 = (idx & 15) * 4;
                float4 y4;
                y4.x = sD1f[(i0 + 0) * 33 + c];
                y4.y = sD1f[(i0 + 1) * 33 + c];
                y4.z = sD1f[(i0 + 2) * 33 + c];
                y4.w = sD1f[(i0 + 3) * 33 + c];
                *(float4*)(yp + c * 64 + i0) = y4;
            }
        }
        __syncthreads();
    }
}

// ---------------- launch --------------------------------------------------------
extern "C" void kernel_launch(void* const* d_in, const int* in_sizes, int n_in,
                              void* d_out, int out_size) {
    const float* u     = (const float*)d_in[0];
    const float* Lr    = (const float*)d_in[1];
    const float* Li    = (const float*)d_in[2];
    const float* Br    = (const float*)d_in[3];
    const float* Bi    = (const float*)d_in[4];
    const float* Cr    = (const float*)d_in[5];
    const float* Ci    = (const float*)d_in[6];
    const float* logdt = (const float*)d_in[7];
    const float* D     = (const float*)d_in[8];
    float* out = (float*)d_out;

    float* ut_ptr;  cudaGetSymbolAddress((void**)&ut_ptr, d_ut);
    float* yt0_ptr; cudaGetSymbolAddress((void**)&yt0_ptr, d_yt0);
    float* yt1_ptr; cudaGetSymbolAddress((void**)&yt1_ptr, d_yt1);

    cudaFuncSetAttribute(fused_kernel, cudaFuncAttributeMaxDynamicSharedMemorySize, SMEM_TOTAL);

    precompute_kernel<<<H_, N_>>>(Lr, Li, Br, Bi, Cr, Ci, logdt, D);
    transpose_BLH_to_BHL<<<dim3(H_ / 32, L_ / 32, B_), 256>>>(u, ut_ptr);
    fused_kernel<<<dim3(4, H_), 256, SMEM_TOTAL>>>();
    transpose_sum_BHL_to_BLH<<<dim3(L_ / 32, H_ / 32, B_), 256>>>(yt0_ptr, yt1_ptr, out);
}

// round 12
// speedup vs baseline: 1.2607x; 1.2607x over previous
#include <cuda_runtime.h>
#include <cuda_fp16.h>
#include <cstdint>

#define B_   16
#define L_   2048
#define H_   512
#define N_   64

// ---------------- fused-kernel dynamic smem layout (byte offsets) ------------
#define oWH  0          // W fp16 [128][72] = 18432 B      (A side: hi only)
#define oA2  18432      // A2: 3 segs x [64][72] fp16 = 27648 B
#define oU   46080      // u tiles: 4 bufs x (hi [32][72] + lo [32][72]) = 36864 B
#define oD1  82944      // D1: 2 batches x [128][36] fp32 = 36864 B (overlaid by D2)
#define oX   119808     // X tiles: 2 batches x (xrH,xrL,xiH,xiL @4608) = 36864 B
#define SMEM_TOTAL 156672

// ---------------- scratch (__device__ globals) --------------------------------
__device__ __align__(16) __half gW  [H_ * 9216];    // per h: [128][72] fp16
__device__ __align__(16) __half gA2 [H_ * 13824];   // per h: 3 segs x [64][72]
__device__ __align__(16) float2 d_AbC[H_ * N_];     // Ab^C
__device__ __align__(16) float  d_ut [B_ * H_ * L_];
__device__ __align__(16) float  d_yt [B_ * H_ * L_];

__device__ __forceinline__ float2 cmul(float2 a, float2 b) {
    return make_float2(a.x * b.x - a.y * b.y, a.x * b.y + a.y * b.x);
}

// ---------------- PTX helpers -------------------------------------------------
__device__ __forceinline__ uint32_t smem_to_u32(const void* p) {
    uint32_t a;
    asm("{ .reg .u64 t; cvta.to.shared.u64 t, %1; cvt.u32.u64 %0, t; }" : "=r"(a) : "l"(p));
    return a;
}
__device__ __forceinline__ void ldm_x4(uint32_t* r, uint32_t addr) {
    asm volatile("ldmatrix.sync.aligned.m8n8.x4.shared.b16 {%0,%1,%2,%3}, [%4];"
                 : "=r"(r[0]), "=r"(r[1]), "=r"(r[2]), "=r"(r[3]) : "r"(addr));
}
__device__ __forceinline__ void ldm_x2(uint32_t* r, uint32_t addr) {
    asm volatile("ldmatrix.sync.aligned.m8n8.x2.shared.b16 {%0,%1}, [%2];"
                 : "=r"(r[0]), "=r"(r[1]) : "r"(addr));
}
__device__ __forceinline__ void mma16816h(float* d, const uint32_t* a, const uint32_t* b) {
    asm volatile("mma.sync.aligned.m16n8k16.row.col.f32.f16.f16.f32 "
                 "{%0,%1,%2,%3}, {%4,%5,%6,%7}, {%8,%9}, {%0,%1,%2,%3};"
                 : "+f"(d[0]), "+f"(d[1]), "+f"(d[2]), "+f"(d[3])
                 : "r"(a[0]), "r"(a[1]), "r"(a[2]), "r"(a[3]), "r"(b[0]), "r"(b[1]));
}

__device__ __forceinline__ void put1h(__half* t, int idx, float v) {
    t[idx] = __float2half_rn(v);
}
__device__ __forceinline__ void put2h(__half* th, __half* tl, int idx, float v) {
    __half hv = __float2half_rn(v);
    th[idx] = hv;
    tl[idx] = __float2half_rn(v - __half2float(hv));
}

// ---------------- precompute (split for ncu launch alignment) -----------------
__global__ void precompute_kernel(const float* __restrict__ Lr,
                                  const float* __restrict__ Li,
                                  const float* __restrict__ Br,
                                  const float* __restrict__ Bi,
                                  const float* __restrict__ Cr,
                                  const float* __restrict__ Ci,
                                  const float* __restrict__ logdt,
                                  const float* __restrict__ Din,
                                  int hofs) {
    int h = blockIdx.x + hofs;
    int n = threadIdx.x;             // 64 threads
    int lane = n & 31, wid = n >> 5;

    float dt  = expf(logdt[h]);
    float lr  = Lr[n], li = Li[n];
    float er = expf(dt * lr);
    float s, c;
    sincosf(dt * li, &s, &c);
    float2 Ab = make_float2(er * c, er * s);

    float dr = lr + 1e-8f, di = li;
    float inv = 1.0f / (dr * dr + di * di);
    float2 Am1 = make_float2(Ab.x - 1.0f, Ab.y);
    float2 Bc  = make_float2(Br[h * N_ + n], Bi[h * N_ + n]);
    float2 num = cmul(Bc, Am1);
    float2 Bb  = make_float2((num.x * dr + num.y * di) * inv,
                             (num.y * dr - num.x * di) * inv);
    float2 Cc  = make_float2(Cr[h * N_ + n], Ci[h * N_ + n]);
    float2 CB  = cmul(Cc, Bb);

    __shared__ float sKpart[64][2];
    __shared__ float sKd[64];

    __half* WH  = gW + (size_t)h * 9216;             // [128][72]
    __half* s0  = gA2 + (size_t)h * 13824;           // Mr
    __half* s1  = s0 + 4608;                         // -Mi
    __half* s2  = s0 + 9216;                         // Toeplitz+D

    float2 p = make_float2(1.0f, 0.0f);              // Ab^e
    for (int e = 0; e < 64; e++) {
        float2 w = cmul(p, Bb);                      // = Ab^{63-j} Bb at j = 63-e
        int j = 63 - e;
        put1h(WH, n * 72 + j, w.x);                  // rows 0..63 : real
        put1h(WH, (64 + n) * 72 + j, w.y);           // rows 64..127 : imag
        float kv = CB.x * p.x - CB.y * p.y;          // K[e] partial (this n)
        #pragma unroll
        for (int off = 16; off; off >>= 1) kv += __shfl_xor_sync(0xffffffffu, kv, off);
        if (lane == 0) sKpart[e][wid] = kv;
        p = cmul(p, Ab);                             // Ab^{e+1}
        float2 m = cmul(Cc, p);                      // M[i=e][n]
        put1h(s0, e * 72 + n, m.x);
        put1h(s1, e * 72 + n, -m.y);
    }
    d_AbC[h * N_ + n] = p;                           // Ab^C
    __syncthreads();
    sKd[n] = sKpart[n][0] + sKpart[n][1];            // K[d = n]
    __syncthreads();

    float Dh = Din[h];
    for (int i = 0; i < 64; i++) {                   // Toeplitz + D on diagonal
        float v = (i > n) ? sKd[i - n] : (i == n ? sKd[0] + Dh : 0.0f);
        put1h(s2, i * 72 + n, v);
    }
}

// ---------------- transposes (float4 both gmem sides) --------------------------
__global__ void transpose_BLH_to_BHL(const float* __restrict__ in, float* __restrict__ out) {
    __shared__ float tile[32][36];
    int b = blockIdx.z;
    int h0 = blockIdx.x * 32, l0 = blockIdx.y * 32;
    int t = threadIdx.x;                 // 256
    {
        int l = t >> 3, hq = t & 7;
        float4 v = *(const float4*)(in + ((size_t)b * L_ + l0 + l) * H_ + h0 + hq * 4);
        tile[hq * 4 + 0][l] = v.x;
        tile[hq * 4 + 1][l] = v.y;
        tile[hq * 4 + 2][l] = v.z;
        tile[hq * 4 + 3][l] = v.w;
    }
    __syncthreads();
    {
        int hh = t >> 3, lq = t & 7;
        float4 w = *(const float4*)&tile[hh][lq * 4];
        *(float4*)(out + ((size_t)b * H_ + h0 + hh) * L_ + l0 + lq * 4) = w;
    }
}

__global__ void transpose_BHL_to_BLH(const float* __restrict__ in, float* __restrict__ out) {
    __shared__ float tile[32][36];
    int b = blockIdx.z;
    int l0 = blockIdx.x * 32, h0 = blockIdx.y * 32;
    int t = threadIdx.x;                 // 256
    {
        int hh = t >> 3, lq = t & 7;
        float4 v = *(const float4*)(in + ((size_t)b * H_ + h0 + hh) * L_ + l0 + lq * 4);
        tile[lq * 4 + 0][hh] = v.x;
        tile[lq * 4 + 1][hh] = v.y;
        tile[lq * 4 + 2][hh] = v.z;
        tile[lq * 4 + 3][hh] = v.w;
    }
    __syncthreads();
    {
        int l = t >> 3, hq = t & 7;
        float4 w = *(const float4*)&tile[l][hq * 4];
        *(float4*)(out + ((size_t)b * L_ + l0 + l) * H_ + h0 + hq * 4) = w;
    }
}

// ---------------- u staging helper (1 float4 per thread per batch) ------------
__device__ __forceinline__ void stage_u1(char* smc, const float* __restrict__ up,
                                         int buf, int tid) {
    float4 v = ((const float4*)up)[tid];
    __half* uh = (__half*)(smc + oU + buf * 9216);
    __half* ul = uh + 2304;
    int idx = (tid >> 4) * 72 + (tid & 15) * 4;
    __half h0 = __float2half_rn(v.x), h1 = __float2half_rn(v.y);
    __half h2 = __float2half_rn(v.z), h3 = __float2half_rn(v.w);
    __half2 p0; p0.x = h0; p0.y = h1;
    __half2 p1; p1.x = h2; p1.y = h3;
    *(__half2*)(uh + idx)     = p0;
    *(__half2*)(uh + idx + 2) = p1;
    __half2 q0, q1;
    q0.x = __float2half_rn(v.x - __half2float(h0));
    q0.y = __float2half_rn(v.y - __half2float(h1));
    q1.x = __float2half_rn(v.z - __half2float(h2));
    q1.y = __float2half_rn(v.w - __half2float(h3));
    *(__half2*)(ul + idx)     = q0;
    *(__half2*)(ul + idx + 2) = q1;
}

// ---------------- fused HMMA kernel: fp16 2-pass, 2 batches per phase ----------
extern __shared__ char smc[];
__global__ __launch_bounds__(512, 1) void fused_kernel() {
    int h   = blockIdx.y;
    int b0  = blockIdx.x * 8;
    int tid = threadIdx.x;
    int w   = tid >> 5, lane = tid & 31;

    uint32_t sb = smem_to_u32(smc);

    // ---- stage operators: W 18432 B + A2 27648 B
    {
        const float4* s = (const float4*)(gW + (size_t)h * 9216);
        float4* d = (float4*)(smc + oWH);
        for (int i = tid; i < 1152; i += 512) d[i] = s[i];
        s = (const float4*)(gA2 + (size_t)h * 13824);
        d = (float4*)(smc + oA2);
        for (int i = tid; i < 1728; i += 512) d[i] = s[i];
    }
    stage_u1(smc, d_ut + ((size_t)b0 * H_ + h) * L_, 0, tid);
    stage_u1(smc, d_ut + ((size_t)(b0 + 1) * H_ + h) * L_, 1, tid);

    // scan constants: n = tid>>3, q = tid&7
    int sn = tid >> 3, sq = tid & 7;
    float2 a1  = d_AbC[h * 64 + sn];
    float2 a2c = cmul(a1, a1);
    float2 a3c = cmul(a2c, a1);
    float2 a4c = cmul(a2c, a2c);
    float2 a8c = cmul(a4c, a4c);
    float2 a16c = cmul(a8c, a8c);
    __syncthreads();

    uint32_t laneA = (uint32_t)(((lane & 15) * 72 + (lane >> 4) * 8) * 2);
    uint32_t laneB = (uint32_t)(((lane & 7) * 72 + ((lane >> 3) & 1) * 8) * 2);

    // MMA1 tiling: mq1 = 16-row m-tile, nh1 = 16-col n-half
    int mq1 = w & 7, nh1 = w >> 3;
    uint32_t w1Hb = sb + oWH + (uint32_t)(mq1 * 16 * 144) + laneA;

    // MMA2 tiling: mq2 m-tile, nh2 n-half, ng k-half (6 k-chunks each)
    int mq2 = w & 3, nh2 = (w >> 2) & 1, ng = w >> 3;
    uint32_t a2H[6][4];                      // 24 regs cached A fragments
    #pragma unroll
    for (int kcl = 0; kcl < 6; kcl++) {
        int kc = ng * 6 + kcl, sg = kc >> 2, kt = kc & 3;
        uint32_t base = sb + oA2 + (uint32_t)(sg * 9216 + mq2 * 16 * 144 + kt * 32) + laneA;
        ldm_x4(a2H[kcl], base);
    }

    float* sD1f = (float*)(smc + oD1);
    int gid = lane >> 2, tq = lane & 3;

    for (int it = 0; it < 4; it++) {
        int bb0 = (2 * it) & 3, bb1 = (2 * it + 1) & 3;

        // ======== P1: MMA1 both batches (2 fp16 passes: Ah*Bh + Ah*Bl) ========
        {
            uint32_t uh0 = sb + oU + (uint32_t)(bb0 * 9216) + laneB, ul0 = uh0 + 4608;
            uint32_t uh1 = sb + oU + (uint32_t)(bb1 * 9216) + laneB, ul1 = uh1 + 4608;
            float acc[2][2][4];
            #pragma unroll
            for (int bt = 0; bt < 2; bt++)
                #pragma unroll
                for (int nt = 0; nt < 2; nt++)
                    #pragma unroll
                    for (int i = 0; i < 4; i++) acc[bt][nt][i] = 0.f;
            #pragma unroll
            for (int kt = 0; kt < 4; kt++) {
                uint32_t ko = kt * 32;
                uint32_t aH[4];
                ldm_x4(aH, w1Hb + ko);
                #pragma unroll
                for (int nt = 0; nt < 2; nt++) {
                    uint32_t bo = (uint32_t)((nh1 * 2 + nt) * 1152) + ko;
                    uint32_t bh[2], bl[2];
                    ldm_x2(bh, uh0 + bo);
                    ldm_x2(bl, ul0 + bo);
                    mma16816h(acc[0][nt], aH, bh);
                    mma16816h(acc[0][nt], aH, bl);
                    ldm_x2(bh, uh1 + bo);
                    ldm_x2(bl, ul1 + bo);
                    mma16816h(acc[1][nt], aH, bh);
                    mma16816h(acc[1][nt], aH, bl);
                }
            }
            #pragma unroll
            for (int bt = 0; bt < 2; bt++)
                #pragma unroll
                for (int nt = 0; nt < 2; nt++) {
                    int c0 = nh1 * 16 + nt * 8 + tq * 2;
                    int r0 = mq1 * 16 + gid;
                    float* D1b = sD1f + bt * 4608;
                    D1b[r0 * 36 + c0]           = acc[bt][nt][0];
                    D1b[r0 * 36 + c0 + 1]       = acc[bt][nt][1];
                    D1b[(r0 + 8) * 36 + c0]     = acc[bt][nt][2];
                    D1b[(r0 + 8) * 36 + c0 + 1] = acc[bt][nt][3];
                }
        }
        __syncthreads();

        // ======== P2: scan both batches + emit X; stage next u ========
        #pragma unroll
        for (int bt = 0; bt < 2; bt++) {
            float* D1b = sD1f + bt * 4608;
            __half* xrH = (__half*)(smc + oX + bt * 18432);
            __half* xrL = xrH + 2304;
            __half* xiH = xrH + 4608;
            __half* xiL = xrH + 6912;

            float4 gr4 = *(const float4*)(D1b + sn * 36 + sq * 4);
            float4 gi4 = *(const float4*)(D1b + (64 + sn) * 36 + sq * 4);
            float h0r = gr4.x, h0i = gi4.x;
            float h1r = a1.x * h0r - a1.y * h0i + gr4.y;
            float h1i = a1.x * h0i + a1.y * h0r + gi4.y;
            float h2r = a1.x * h1r - a1.y * h1i + gr4.z;
            float h2i = a1.x * h1i + a1.y * h1r + gi4.z;
            float Sr  = a1.x * h2r - a1.y * h2i + gr4.w;
            float Si  = a1.x * h2i + a1.y * h2r + gi4.w;
            float tr, ti;
            tr = __shfl_up_sync(0xffffffffu, Sr, 1, 8);
            ti = __shfl_up_sync(0xffffffffu, Si, 1, 8);
            if (sq >= 1) { Sr += a4c.x * tr - a4c.y * ti;  Si += a4c.x * ti + a4c.y * tr; }
            tr = __shfl_up_sync(0xffffffffu, Sr, 2, 8);
            ti = __shfl_up_sync(0xffffffffu, Si, 2, 8);
            if (sq >= 2) { Sr += a8c.x * tr - a8c.y * ti;  Si += a8c.x * ti + a8c.y * tr; }
            tr = __shfl_up_sync(0xffffffffu, Sr, 4, 8);
            ti = __shfl_up_sync(0xffffffffu, Si, 4, 8);
            if (sq >= 4) { Sr += a16c.x * tr - a16c.y * ti; Si += a16c.x * ti + a16c.y * tr; }
            float X0r = __shfl_up_sync(0xffffffffu, Sr, 1, 8);
            float X0i = __shfl_up_sync(0xffffffffu, Si, 1, 8);
            if (sq == 0) { X0r = 0.f; X0i = 0.f; }

            int idx = (sq * 4) * 72 + sn;
            put2h(xrH, xrL, idx, X0r);
            put2h(xiH, xiL, idx, X0i);
            float pr = a1.x * X0r - a1.y * X0i + h0r;
            float pi = a1.x * X0i + a1.y * X0r + h0i;
            put2h(xrH, xrL, idx + 72, pr);
            put2h(xiH, xiL, idx + 72, pi);
            pr = a2c.x * X0r - a2c.y * X0i + h1r;
            pi = a2c.x * X0i + a2c.y * X0r + h1i;
            put2h(xrH, xrL, idx + 144, pr);
            put2h(xiH, xiL, idx + 144, pi);
            pr = a3c.x * X0r - a3c.y * X0i + h2r;
            pi = a3c.x * X0i + a3c.y * X0r + h2i;
            put2h(xrH, xrL, idx + 216, pr);
            put2h(xiH, xiL, idx + 216, pi);
        }
        if (it < 3) {
            stage_u1(smc, d_ut + ((size_t)(b0 + 2 * it + 2) * H_ + h) * L_, (2 * it + 2) & 3, tid);
            stage_u1(smc, d_ut + ((size_t)(b0 + 2 * it + 3) * H_ + h) * L_, (2 * it + 3) & 3, tid);
        }
        __syncthreads();

        // ======== P3: MMA2 both batches (2 fp16 passes; D2 overlays D1) ========
        #pragma unroll
        for (int bt = 0; bt < 2; bt++) {
            uint32_t uhBp = sb + oU + (uint32_t)(((2 * it + bt) & 3) * 9216) + laneB;
            float acc[2][4];
            #pragma unroll
            for (int nt = 0; nt < 2; nt++)
                #pragma unroll
                for (int i = 0; i < 4; i++) acc[nt][i] = 0.f;
            #pragma unroll
            for (int kcl = 0; kcl < 6; kcl++) {
                int kc = ng * 6 + kcl, sg = kc >> 2, kt = kc & 3;
                uint32_t ko = kt * 32;
                uint32_t bHB = (sg == 2)
                    ? (uhBp + ko)
                    : (sb + oX + (uint32_t)(bt * 18432 + sg * 9216) + laneB + ko);
                uint32_t bLB = bHB + 4608;
                #pragma unroll
                for (int nt = 0; nt < 2; nt++) {
                    uint32_t bo = (uint32_t)((nh2 * 2 + nt) * 1152);
                    uint32_t bh[2], bl[2];
                    ldm_x2(bh, bHB + bo);
                    ldm_x2(bl, bLB + bo);
                    mma16816h(acc[nt], a2H[kcl], bh);
                    mma16816h(acc[nt], a2H[kcl], bl);
                }
            }
            float* sD2 = sD1f + (bt * 2 + ng) * 2112;
            #pragma unroll
            for (int nt = 0; nt < 2; nt++) {
                int c0 = nh2 * 16 + nt * 8 + tq * 2;
                int i0 = mq2 * 16 + gid;
                sD2[i0 * 33 + c0]           = acc[nt][0];
                sD2[i0 * 33 + c0 + 1]       = acc[nt][1];
                sD2[(i0 + 8) * 33 + c0]     = acc[nt][2];
                sD2[(i0 + 8) * 33 + c0 + 1] = acc[nt][3];
            }
        }
        __syncthreads();

        // ======== P4: store y both batches ========
        {
            int bt = tid >> 8, t = tid & 255;
            float* sD2a = sD1f + bt * 2 * 2112;
            float* yp = d_yt + ((size_t)(b0 + 2 * it + bt) * H_ + h) * L_;
            #pragma unroll
            for (int rep = 0; rep < 2; rep++) {
                int idx = rep * 256 + t;
                int c = idx >> 4, i0 = (idx & 15) * 4;
                float4 y4;
                y4.x = sD2a[(i0 + 0) * 33 + c] + sD2a[2112 + (i0 + 0) * 33 + c];
                y4.y = sD2a[(i0 + 1) * 33 + c] + sD2a[2112 + (i0 + 1) * 33 + c];
                y4.z = sD2a[(i0 + 2) * 33 + c] + sD2a[2112 + (i0 + 2) * 33 + c];
                y4.w = sD2a[(i0 + 3) * 33 + c] + sD2a[2112 + (i0 + 3) * 33 + c];
                *(float4*)(yp + c * 64 + i0) = y4;
            }
        }
        __syncthreads();
    }
}

// ---------------- launch --------------------------------------------------------
extern "C" void kernel_launch(void* const* d_in, const int* in_sizes, int n_in,
                              void* d_out, int out_size) {
    const float* u     = (const float*)d_in[0];
    const float* Lr    = (const float*)d_in[1];
    const float* Li    = (const float*)d_in[2];
    const float* Br    = (const float*)d_in[3];
    const float* Bi    = (const float*)d_in[4];
    const float* Cr    = (const float*)d_in[5];
    const float* Ci    = (const float*)d_in[6];
    const float* logdt = (const float*)d_in[7];
    const float* D     = (const float*)d_in[8];
    float* out = (float*)d_out;

    float* ut_ptr; cudaGetSymbolAddress((void**)&ut_ptr, d_ut);
    float* yt_ptr; cudaGetSymbolAddress((void**)&yt_ptr, d_yt);

    cudaFuncSetAttribute(fused_kernel, cudaFuncAttributeMaxDynamicSharedMemorySize, SMEM_TOTAL);

    // precompute split into two launches (also aligns ncu's skip-5 capture
    // onto fused_kernel instead of a transpose)
    precompute_kernel<<<H_ / 2, N_>>>(Lr, Li, Br, Bi, Cr, Ci, logdt, D, 0);
    precompute_kernel<<<H_ / 2, N_>>>(Lr, Li, Br, Bi, Cr, Ci, logdt, D, H_ / 2);
    transpose_BLH_to_BHL<<<dim3(H_ / 32, L_ / 32, B_), 256>>>(u, ut_ptr);
    fused_kernel<<<dim3(2, H_), 512, SMEM_TOTAL>>>();
    transpose_BHL_to_BLH<<<dim3(L_ / 32, H_ / 32, B_), 256>>>(yt_ptr, out);
}

// round 13
// speedup vs baseline: 1.4822x; 1.1757x over previous
#include <cuda_runtime.h>
#include <cuda_fp16.h>
#include <cstdint>

#define B_   16
#define L_   2048
#define H_   512
#define N_   64

// ---------------- fused-kernel dynamic smem layout (byte offsets) ------------
#define oWH  0          // W fp16 [128][72] = 18432 B
#define oA2  18432      // A2: 3 segs x [64][72] fp16 = 27648 B
#define oU   46080      // u tiles: 4 bufs x [32][72] fp16 = 18432 B
#define oD1  64512      // D1: 2 batches x [128][36] fp32 = 36864 B (overlaid by D2)
#define oX   101376     // X tiles: 2 batches x (xrH, xiH @4608) = 18432 B
#define SMEM_TOTAL 119808

// ---------------- scratch (__device__ globals) --------------------------------
__device__ __align__(16) __half gW  [H_ * 9216];    // per h: [128][72] fp16
__device__ __align__(16) __half gA2 [H_ * 13824];   // per h: 3 segs x [64][72]
__device__ __align__(16) float2 d_AbC[H_ * N_];     // Ab^C
__device__ __align__(16) float  d_ut [B_ * H_ * L_];
__device__ __align__(16) float  d_yt [B_ * H_ * L_];

__device__ __forceinline__ float2 cmul(float2 a, float2 b) {
    return make_float2(a.x * b.x - a.y * b.y, a.x * b.y + a.y * b.x);
}

// ---------------- PTX helpers -------------------------------------------------
__device__ __forceinline__ uint32_t smem_to_u32(const void* p) {
    uint32_t a;
    asm("{ .reg .u64 t; cvta.to.shared.u64 t, %1; cvt.u32.u64 %0, t; }" : "=r"(a) : "l"(p));
    return a;
}
__device__ __forceinline__ void ldm_x4(uint32_t* r, uint32_t addr) {
    asm volatile("ldmatrix.sync.aligned.m8n8.x4.shared.b16 {%0,%1,%2,%3}, [%4];"
                 : "=r"(r[0]), "=r"(r[1]), "=r"(r[2]), "=r"(r[3]) : "r"(addr));
}
__device__ __forceinline__ void ldm_x2(uint32_t* r, uint32_t addr) {
    asm volatile("ldmatrix.sync.aligned.m8n8.x2.shared.b16 {%0,%1}, [%2];"
                 : "=r"(r[0]), "=r"(r[1]) : "r"(addr));
}
__device__ __forceinline__ void mma16816h(float* d, const uint32_t* a, const uint32_t* b) {
    asm volatile("mma.sync.aligned.m16n8k16.row.col.f32.f16.f16.f32 "
                 "{%0,%1,%2,%3}, {%4,%5,%6,%7}, {%8,%9}, {%0,%1,%2,%3};"
                 : "+f"(d[0]), "+f"(d[1]), "+f"(d[2]), "+f"(d[3])
                 : "r"(a[0]), "r"(a[1]), "r"(a[2]), "r"(a[3]), "r"(b[0]), "r"(b[1]));
}

__device__ __forceinline__ void put1h(__half* t, int idx, float v) {
    t[idx] = __float2half_rn(v);
}

// ---------------- precompute (split across 2 launches) ------------------------
__global__ void precompute_kernel(const float* __restrict__ Lr,
                                  const float* __restrict__ Li,
                                  const float* __restrict__ Br,
                                  const float* __restrict__ Bi,
                                  const float* __restrict__ Cr,
                                  const float* __restrict__ Ci,
                                  const float* __restrict__ logdt,
                                  const float* __restrict__ Din,
                                  int hofs) {
    int h = blockIdx.x + hofs;
    int n = threadIdx.x;             // 64 threads
    int lane = n & 31, wid = n >> 5;

    float dt  = expf(logdt[h]);
    float lr  = Lr[n], li = Li[n];
    float er = expf(dt * lr);
    float s, c;
    sincosf(dt * li, &s, &c);
    float2 Ab = make_float2(er * c, er * s);

    float dr = lr + 1e-8f, di = li;
    float inv = 1.0f / (dr * dr + di * di);
    float2 Am1 = make_float2(Ab.x - 1.0f, Ab.y);
    float2 Bc  = make_float2(Br[h * N_ + n], Bi[h * N_ + n]);
    float2 num = cmul(Bc, Am1);
    float2 Bb  = make_float2((num.x * dr + num.y * di) * inv,
                             (num.y * dr - num.x * di) * inv);
    float2 Cc  = make_float2(Cr[h * N_ + n], Ci[h * N_ + n]);
    float2 CB  = cmul(Cc, Bb);

    __shared__ float sKpart[64][2];
    __shared__ float sKd[64];

    __half* WH  = gW + (size_t)h * 9216;             // [128][72]
    __half* s0  = gA2 + (size_t)h * 13824;           // Mr
    __half* s1  = s0 + 4608;                         // -Mi
    __half* s2  = s0 + 9216;                         // Toeplitz+D

    float2 p = make_float2(1.0f, 0.0f);              // Ab^e
    for (int e = 0; e < 64; e++) {
        float2 w = cmul(p, Bb);                      // = Ab^{63-j} Bb at j = 63-e
        int j = 63 - e;
        put1h(WH, n * 72 + j, w.x);                  // rows 0..63 : real
        put1h(WH, (64 + n) * 72 + j, w.y);           // rows 64..127 : imag
        float kv = CB.x * p.x - CB.y * p.y;          // K[e] partial (this n)
        #pragma unroll
        for (int off = 16; off; off >>= 1) kv += __shfl_xor_sync(0xffffffffu, kv, off);
        if (lane == 0) sKpart[e][wid] = kv;
        p = cmul(p, Ab);                             // Ab^{e+1}
        float2 m = cmul(Cc, p);                      // M[i=e][n]
        put1h(s0, e * 72 + n, m.x);
        put1h(s1, e * 72 + n, -m.y);
    }
    d_AbC[h * N_ + n] = p;                           // Ab^C
    __syncthreads();
    sKd[n] = sKpart[n][0] + sKpart[n][1];            // K[d = n]
    __syncthreads();

    float Dh = Din[h];
    for (int i = 0; i < 64; i++) {                   // Toeplitz + D on diagonal
        float v = (i > n) ? sKd[i - n] : (i == n ? sKd[0] + Dh : 0.0f);
        put1h(s2, i * 72 + n, v);
    }
}

// ---------------- transposes (float4 both gmem sides) --------------------------
__global__ void transpose_BLH_to_BHL(const float* __restrict__ in, float* __restrict__ out) {
    __shared__ float tile[32][36];
    int b = blockIdx.z;
    int h0 = blockIdx.x * 32, l0 = blockIdx.y * 32;
    int t = threadIdx.x;                 // 256
    {
        int l = t >> 3, hq = t & 7;
        float4 v = *(const float4*)(in + ((size_t)b * L_ + l0 + l) * H_ + h0 + hq * 4);
        tile[hq * 4 + 0][l] = v.x;
        tile[hq * 4 + 1][l] = v.y;
        tile[hq * 4 + 2][l] = v.z;
        tile[hq * 4 + 3][l] = v.w;
    }
    __syncthreads();
    {
        int hh = t >> 3, lq = t & 7;
        float4 w = *(const float4*)&tile[hh][lq * 4];
        *(float4*)(out + ((size_t)b * H_ + h0 + hh) * L_ + l0 + lq * 4) = w;
    }
}

__global__ void transpose_BHL_to_BLH(const float* __restrict__ in, float* __restrict__ out) {
    __shared__ float tile[32][36];
    int b = blockIdx.z;
    int l0 = blockIdx.x * 32, h0 = blockIdx.y * 32;
    int t = threadIdx.x;                 // 256
    {
        int hh = t >> 3, lq = t & 7;
        float4 v = *(const float4*)(in + ((size_t)b * H_ + h0 + hh) * L_ + l0 + lq * 4);
        tile[lq * 4 + 0][hh] = v.x;
        tile[lq * 4 + 1][hh] = v.y;
        tile[lq * 4 + 2][hh] = v.z;
        tile[lq * 4 + 3][hh] = v.w;
    }
    __syncthreads();
    {
        int l = t >> 3, hq = t & 7;
        float4 w = *(const float4*)&tile[l][hq * 4];
        *(float4*)(out + ((size_t)b * L_ + l0 + l) * H_ + h0 + hq * 4) = w;
    }
}

// ---------------- u staging: fp32 -> fp16 padded tile (hi only) ---------------
__device__ __forceinline__ void stage_u1(char* smc, const float* __restrict__ up,
                                         int buf, int tid) {
    float4 v = ((const float4*)up)[tid];
    __half* uh = (__half*)(smc + oU + buf * 4608);
    int idx = (tid >> 4) * 72 + (tid & 15) * 4;
    __half2 p0; p0.x = __float2half_rn(v.x); p0.y = __float2half_rn(v.y);
    __half2 p1; p1.x = __float2half_rn(v.z); p1.y = __float2half_rn(v.w);
    *(__half2*)(uh + idx)     = p0;
    *(__half2*)(uh + idx + 2) = p1;
}

// ---------------- fused HMMA kernel: fp16 single-pass, 2 batches per phase ----
extern __shared__ char smc[];
__global__ __launch_bounds__(512, 1) void fused_kernel() {
    int h   = blockIdx.y;
    int b0  = blockIdx.x * 8;
    int tid = threadIdx.x;
    int w   = tid >> 5, lane = tid & 31;

    uint32_t sb = smem_to_u32(smc);

    // ---- stage operators: W 18432 B + A2 27648 B
    {
        const float4* s = (const float4*)(gW + (size_t)h * 9216);
        float4* d = (float4*)(smc + oWH);
        for (int i = tid; i < 1152; i += 512) d[i] = s[i];
        s = (const float4*)(gA2 + (size_t)h * 13824);
        d = (float4*)(smc + oA2);
        for (int i = tid; i < 1728; i += 512) d[i] = s[i];
    }
    stage_u1(smc, d_ut + ((size_t)b0 * H_ + h) * L_, 0, tid);
    stage_u1(smc, d_ut + ((size_t)(b0 + 1) * H_ + h) * L_, 1, tid);

    // scan constants: n = tid>>3, q = tid&7
    int sn = tid >> 3, sq = tid & 7;
    float2 a1  = d_AbC[h * 64 + sn];
    float2 a2c = cmul(a1, a1);
    float2 a3c = cmul(a2c, a1);
    float2 a4c = cmul(a2c, a2c);
    float2 a8c = cmul(a4c, a4c);
    float2 a16c = cmul(a8c, a8c);
    __syncthreads();

    uint32_t laneA = (uint32_t)(((lane & 15) * 72 + (lane >> 4) * 8) * 2);
    uint32_t laneB = (uint32_t)(((lane & 7) * 72 + ((lane >> 3) & 1) * 8) * 2);

    // MMA1 tiling: mq1 = 16-row m-tile, nh1 = 16-col n-half; W frags cached
    int mq1 = w & 7, nh1 = w >> 3;
    uint32_t w1A[4][4];
    {
        uint32_t w1Hb = sb + oWH + (uint32_t)(mq1 * 16 * 144) + laneA;
        #pragma unroll
        for (int kt = 0; kt < 4; kt++) ldm_x4(w1A[kt], w1Hb + (uint32_t)(kt * 32));
    }

    // MMA2 tiling: mq2 m-tile, nh2 n-half, ng k-half (6 k-chunks each); cached
    int mq2 = w & 3, nh2 = (w >> 2) & 1, ng = w >> 3;
    uint32_t a2A[6][4];
    #pragma unroll
    for (int kcl = 0; kcl < 6; kcl++) {
        int kc = ng * 6 + kcl, sg = kc >> 2, kt = kc & 3;
        uint32_t base = sb + oA2 + (uint32_t)(sg * 9216 + mq2 * 16 * 144 + kt * 32) + laneA;
        ldm_x4(a2A[kcl], base);
    }

    float* sD1f = (float*)(smc + oD1);
    int gid = lane >> 2, tq = lane & 3;

    for (int it = 0; it < 4; it++) {
        int bb0 = (2 * it) & 3, bb1 = (2 * it + 1) & 3;

        // ======== P1: MMA1 both batches (single fp16 pass) ========
        {
            uint32_t uh0 = sb + oU + (uint32_t)(bb0 * 4608) + laneB;
            uint32_t uh1 = sb + oU + (uint32_t)(bb1 * 4608) + laneB;
            float acc[2][2][4];
            #pragma unroll
            for (int bt = 0; bt < 2; bt++)
                #pragma unroll
                for (int nt = 0; nt < 2; nt++)
                    #pragma unroll
                    for (int i = 0; i < 4; i++) acc[bt][nt][i] = 0.f;
            #pragma unroll
            for (int kt = 0; kt < 4; kt++) {
                uint32_t ko = kt * 32;
                #pragma unroll
                for (int nt = 0; nt < 2; nt++) {
                    uint32_t bo = (uint32_t)((nh1 * 2 + nt) * 1152) + ko;
                    uint32_t bh[2];
                    ldm_x2(bh, uh0 + bo);
                    mma16816h(acc[0][nt], w1A[kt], bh);
                    ldm_x2(bh, uh1 + bo);
                    mma16816h(acc[1][nt], w1A[kt], bh);
                }
            }
            #pragma unroll
            for (int bt = 0; bt < 2; bt++)
                #pragma unroll
                for (int nt = 0; nt < 2; nt++) {
                    int c0 = nh1 * 16 + nt * 8 + tq * 2;
                    int r0 = mq1 * 16 + gid;
                    float* D1b = sD1f + bt * 4608;
                    D1b[r0 * 36 + c0]           = acc[bt][nt][0];
                    D1b[r0 * 36 + c0 + 1]       = acc[bt][nt][1];
                    D1b[(r0 + 8) * 36 + c0]     = acc[bt][nt][2];
                    D1b[(r0 + 8) * 36 + c0 + 1] = acc[bt][nt][3];
                }
        }
        __syncthreads();

        // ======== P2: scan both batches + emit X (fp16); stage next u ========
        #pragma unroll
        for (int bt = 0; bt < 2; bt++) {
            float* D1b = sD1f + bt * 4608;
            __half* xrH = (__half*)(smc + oX + bt * 9216);
            __half* xiH = xrH + 2304;

            float4 gr4 = *(const float4*)(D1b + sn * 36 + sq * 4);
            float4 gi4 = *(const float4*)(D1b + (64 + sn) * 36 + sq * 4);
            float h0r = gr4.x, h0i = gi4.x;
            float h1r = a1.x * h0r - a1.y * h0i + gr4.y;
            float h1i = a1.x * h0i + a1.y * h0r + gi4.y;
            float h2r = a1.x * h1r - a1.y * h1i + gr4.z;
            float h2i = a1.x * h1i + a1.y * h1r + gi4.z;
            float Sr  = a1.x * h2r - a1.y * h2i + gr4.w;
            float Si  = a1.x * h2i + a1.y * h2r + gi4.w;
            float tr, ti;
            tr = __shfl_up_sync(0xffffffffu, Sr, 1, 8);
            ti = __shfl_up_sync(0xffffffffu, Si, 1, 8);
            if (sq >= 1) { Sr += a4c.x * tr - a4c.y * ti;  Si += a4c.x * ti + a4c.y * tr; }
            tr = __shfl_up_sync(0xffffffffu, Sr, 2, 8);
            ti = __shfl_up_sync(0xffffffffu, Si, 2, 8);
            if (sq >= 2) { Sr += a8c.x * tr - a8c.y * ti;  Si += a8c.x * ti + a8c.y * tr; }
            tr = __shfl_up_sync(0xffffffffu, Sr, 4, 8);
            ti = __shfl_up_sync(0xffffffffu, Si, 4, 8);
            if (sq >= 4) { Sr += a16c.x * tr - a16c.y * ti; Si += a16c.x * ti + a16c.y * tr; }
            float X0r = __shfl_up_sync(0xffffffffu, Sr, 1, 8);
            float X0i = __shfl_up_sync(0xffffffffu, Si, 1, 8);
            if (sq == 0) { X0r = 0.f; X0i = 0.f; }

            int idx = (sq * 4) * 72 + sn;
            put1h(xrH, idx, X0r);
            put1h(xiH, idx, X0i);
            float pr = a1.x * X0r - a1.y * X0i + h0r;
            float pi = a1.x * X0i + a1.y * X0r + h0i;
            put1h(xrH, idx + 72, pr);
            put1h(xiH, idx + 72, pi);
            pr = a2c.x * X0r - a2c.y * X0i + h1r;
            pi = a2c.x * X0i + a2c.y * X0r + h1i;
            put1h(xrH, idx + 144, pr);
            put1h(xiH, idx + 144, pi);
            pr = a3c.x * X0r - a3c.y * X0i + h2r;
            pi = a3c.x * X0i + a3c.y * X0r + h2i;
            put1h(xrH, idx + 216, pr);
            put1h(xiH, idx + 216, pi);
        }
        if (it < 3) {
            stage_u1(smc, d_ut + ((size_t)(b0 + 2 * it + 2) * H_ + h) * L_, (2 * it + 2) & 3, tid);
            stage_u1(smc, d_ut + ((size_t)(b0 + 2 * it + 3) * H_ + h) * L_, (2 * it + 3) & 3, tid);
        }
        __syncthreads();

        // ======== P3: MMA2 both batches (single fp16 pass; D2 overlays D1) ====
        #pragma unroll
        for (int bt = 0; bt < 2; bt++) {
            uint32_t uhBp = sb + oU + (uint32_t)(((2 * it + bt) & 3) * 4608) + laneB;
            float acc[2][4];
            #pragma unroll
            for (int nt = 0; nt < 2; nt++)
                #pragma unroll
                for (int i = 0; i < 4; i++) acc[nt][i] = 0.f;
            #pragma unroll
            for (int kcl = 0; kcl < 6; kcl++) {
                int kc = ng * 6 + kcl, sg = kc >> 2, kt = kc & 3;
                uint32_t ko = kt * 32;
                uint32_t bHB = (sg == 2)
                    ? (uhBp + ko)
                    : (sb + oX + (uint32_t)(bt * 9216 + sg * 4608) + laneB + ko);
                #pragma unroll
                for (int nt = 0; nt < 2; nt++) {
                    uint32_t bo = (uint32_t)((nh2 * 2 + nt) * 1152);
                    uint32_t bh[2];
                    ldm_x2(bh, bHB + bo);
                    mma16816h(acc[nt], a2A[kcl], bh);
                }
            }
            float* sD2 = sD1f + (bt * 2 + ng) * 2112;
            #pragma unroll
            for (int nt = 0; nt < 2; nt++) {
                int c0 = nh2 * 16 + nt * 8 + tq * 2;
                int i0 = mq2 * 16 + gid;
                sD2[i0 * 33 + c0]           = acc[nt][0];
                sD2[i0 * 33 + c0 + 1]       = acc[nt][1];
                sD2[(i0 + 8) * 33 + c0]     = acc[nt][2];
                sD2[(i0 + 8) * 33 + c0 + 1] = acc[nt][3];
            }
        }
        __syncthreads();

        // ======== P4: store y both batches ========
        {
            int bt = tid >> 8, t = tid & 255;
            float* sD2a = sD1f + bt * 2 * 2112;
            float* yp = d_yt + ((size_t)(b0 + 2 * it + bt) * H_ + h) * L_;
            #pragma unroll
            for (int rep = 0; rep < 2; rep++) {
                int idx = rep * 256 + t;
                int c = idx >> 4, i0 = (idx & 15) * 4;
                float4 y4;
                y4.x = sD2a[(i0 + 0) * 33 + c] + sD2a[2112 + (i0 + 0) * 33 + c];
                y4.y = sD2a[(i0 + 1) * 33 + c] + sD2a[2112 + (i0 + 1) * 33 + c];
                y4.z = sD2a[(i0 + 2) * 33 + c] + sD2a[2112 + (i0 + 2) * 33 + c];
                y4.w = sD2a[(i0 + 3) * 33 + c] + sD2a[2112 + (i0 + 3) * 33 + c];
                *(float4*)(yp + c * 64 + i0) = y4;
            }
        }
        __syncthreads();
    }
}

// ---------------- launch --------------------------------------------------------
extern "C" void kernel_launch(void* const* d_in, const int* in_sizes, int n_in,
                              void* d_out, int out_size) {
    const float* u     = (const float*)d_in[0];
    const float* Lr    = (const float*)d_in[1];
    const float* Li    = (const float*)d_in[2];
    const float* Br    = (const float*)d_in[3];
    const float* Bi    = (const float*)d_in[4];
    const float* Cr    = (const float*)d_in[5];
    const float* Ci    = (const float*)d_in[6];
    const float* logdt = (const float*)d_in[7];
    const float* D     = (const float*)d_in[8];
    float* out = (float*)d_out;

    float* ut_ptr; cudaGetSymbolAddress((void**)&ut_ptr, d_ut);
    float* yt_ptr; cudaGetSymbolAddress((void**)&yt_ptr, d_yt);

    cudaFuncSetAttribute(fused_kernel, cudaFuncAttributeMaxDynamicSharedMemorySize, SMEM_TOTAL);

    precompute_kernel<<<H_ / 2, N_>>>(Lr, Li, Br, Bi, Cr, Ci, logdt, D, 0);
    precompute_kernel<<<H_ / 2, N_>>>(Lr, Li, Br, Bi, Cr, Ci, logdt, D, H_ / 2);
    transpose_BLH_to_BHL<<<dim3(H_ / 32, L_ / 32, B_), 256>>>(u, ut_ptr);
    fused_kernel<<<dim3(2, H_), 512, SMEM_TOTAL>>>();
    transpose_BHL_to_BLH<<<dim3(L_ / 32, H_ / 32, B_), 256>>>(yt_ptr, out);
}

// round 15
// speedup vs baseline: 1.5496x; 1.0455x over previous
#include <cuda_runtime.h>
#include <cuda_fp16.h>
#include <cstdint>

#define B_   16
#define L_   2048
#define H_   512
#define N_   64

// ---------------- fused-kernel dynamic smem layout (byte offsets) ------------
#define oWH  0          // W fp16 [128][72] = 18432 B
#define oA2  18432      // A2: 3 segs x [64][72] fp16 = 27648 B
#define oU   46080      // u tiles: 4 bufs x [32][72] fp16 = 18432 B
#define oD1  64512      // D1: 2 batches x [128][36] fp32 = 36864 B (overlaid by D2)
#define oX   101376     // X tiles (k-major): 2 batches x [128][40] fp16 = 20480 B
#define SMEM_TOTAL 121856

// ---------------- scratch (__device__ globals) --------------------------------
__device__ __align__(16) __half gW  [H_ * 9216];    // per h: [128][72] fp16
__device__ __align__(16) __half gA2 [H_ * 13824];   // per h: 3 segs x [64][72]
__device__ __align__(16) float2 d_AbC[H_ * N_];     // Ab^C
__device__ __align__(16) float  d_ut [B_ * H_ * L_];
__device__ __align__(16) float  d_yt [B_ * H_ * L_];

__device__ __forceinline__ float2 cmul(float2 a, float2 b) {
    return make_float2(a.x * b.x - a.y * b.y, a.x * b.y + a.y * b.x);
}

// ---------------- PTX helpers -------------------------------------------------
__device__ __forceinline__ uint32_t smem_to_u32(const void* p) {
    uint32_t a;
    asm("{ .reg .u64 t; cvta.to.shared.u64 t, %1; cvt.u32.u64 %0, t; }" : "=r"(a) : "l"(p));
    return a;
}
__device__ __forceinline__ void ldm_x4(uint32_t* r, uint32_t addr) {
    asm volatile("ldmatrix.sync.aligned.m8n8.x4.shared.b16 {%0,%1,%2,%3}, [%4];"
                 : "=r"(r[0]), "=r"(r[1]), "=r"(r[2]), "=r"(r[3]) : "r"(addr));
}
__device__ __forceinline__ void ldm_x2(uint32_t* r, uint32_t addr) {
    asm volatile("ldmatrix.sync.aligned.m8n8.x2.shared.b16 {%0,%1}, [%2];"
                 : "=r"(r[0]), "=r"(r[1]) : "r"(addr));
}
__device__ __forceinline__ void ldm_x2t(uint32_t* r, uint32_t addr) {
    asm volatile("ldmatrix.sync.aligned.m8n8.x2.trans.shared.b16 {%0,%1}, [%2];"
                 : "=r"(r[0]), "=r"(r[1]) : "r"(addr));
}
__device__ __forceinline__ void mma16816h(float* d, const uint32_t* a, const uint32_t* b) {
    asm volatile("mma.sync.aligned.m16n8k16.row.col.f32.f16.f16.f32 "
                 "{%0,%1,%2,%3}, {%4,%5,%6,%7}, {%8,%9}, {%0,%1,%2,%3};"
                 : "+f"(d[0]), "+f"(d[1]), "+f"(d[2]), "+f"(d[3])
                 : "r"(a[0]), "r"(a[1]), "r"(a[2]), "r"(a[3]), "r"(b[0]), "r"(b[1]));
}

__device__ __forceinline__ void put1h(__half* t, int idx, float v) {
    t[idx] = __float2half_rn(v);
}

// ---------------- precompute (split across 2 launches) ------------------------
__global__ void precompute_kernel(const float* __restrict__ Lr,
                                  const float* __restrict__ Li,
                                  const float* __restrict__ Br,
                                  const float* __restrict__ Bi,
                                  const float* __restrict__ Cr,
                                  const float* __restrict__ Ci,
                                  const float* __restrict__ logdt,
                                  const float* __restrict__ Din,
                                  int hofs) {
    int h = blockIdx.x + hofs;
    int n = threadIdx.x;             // 64 threads
    int lane = n & 31, wid = n >> 5;

    float dt  = expf(logdt[h]);
    float lr  = Lr[n], li = Li[n];
    float er = expf(dt * lr);
    float s, c;
    sincosf(dt * li, &s, &c);
    float2 Ab = make_float2(er * c, er * s);

    float dr = lr + 1e-8f, di = li;
    float inv = 1.0f / (dr * dr + di * di);
    float2 Am1 = make_float2(Ab.x - 1.0f, Ab.y);
    float2 Bc  = make_float2(Br[h * N_ + n], Bi[h * N_ + n]);
    float2 num = cmul(Bc, Am1);
    float2 Bb  = make_float2((num.x * dr + num.y * di) * inv,
                             (num.y * dr - num.x * di) * inv);
    float2 Cc  = make_float2(Cr[h * N_ + n], Ci[h * N_ + n]);
    float2 CB  = cmul(Cc, Bb);

    __shared__ float sKpart[64][2];
    __shared__ float sKd[64];

    __half* WH  = gW + (size_t)h * 9216;             // [128][72]
    __half* s0  = gA2 + (size_t)h * 13824;           // Mr
    __half* s1  = s0 + 4608;                         // -Mi
    __half* s2  = s0 + 9216;                         // Toeplitz+D

    float2 p = make_float2(1.0f, 0.0f);              // Ab^e
    for (int e = 0; e < 64; e++) {
        float2 w = cmul(p, Bb);                      // = Ab^{63-j} Bb at j = 63-e
        int j = 63 - e;
        put1h(WH, n * 72 + j, w.x);                  // rows 0..63 : real
        put1h(WH, (64 + n) * 72 + j, w.y);           // rows 64..127 : imag
        float kv = CB.x * p.x - CB.y * p.y;          // K[e] partial (this n)
        #pragma unroll
        for (int off = 16; off; off >>= 1) kv += __shfl_xor_sync(0xffffffffu, kv, off);
        if (lane == 0) sKpart[e][wid] = kv;
        p = cmul(p, Ab);                             // Ab^{e+1}
        float2 m = cmul(Cc, p);                      // M[i=e][n]
        put1h(s0, e * 72 + n, m.x);
        put1h(s1, e * 72 + n, -m.y);
    }
    d_AbC[h * N_ + n] = p;                           // Ab^C
    __syncthreads();
    sKd[n] = sKpart[n][0] + sKpart[n][1];            // K[d = n]
    __syncthreads();

    float Dh = Din[h];
    for (int i = 0; i < 64; i++) {                   // Toeplitz + D on diagonal
        float v = (i > n) ? sKd[i - n] : (i == n ? sKd[0] + Dh : 0.0f);
        put1h(s2, i * 72 + n, v);
    }
}

// ---------------- transposes (float4 both gmem sides) --------------------------
__global__ void transpose_BLH_to_BHL(const float* __restrict__ in, float* __restrict__ out) {
    __shared__ float tile[32][36];
    int b = blockIdx.z;
    int h0 = blockIdx.x * 32, l0 = blockIdx.y * 32;
    int t = threadIdx.x;                 // 256
    {
        int l = t >> 3, hq = t & 7;
        float4 v = *(const float4*)(in + ((size_t)b * L_ + l0 + l) * H_ + h0 + hq * 4);
        tile[hq * 4 + 0][l] = v.x;
        tile[hq * 4 + 1][l] = v.y;
        tile[hq * 4 + 2][l] = v.z;
        tile[hq * 4 + 3][l] = v.w;
    }
    __syncthreads();
    {
        int hh = t >> 3, lq = t & 7;
        float4 w = *(const float4*)&tile[hh][lq * 4];
        *(float4*)(out + ((size_t)b * H_ + h0 + hh) * L_ + l0 + lq * 4) = w;
    }
}

__global__ void transpose_BHL_to_BLH(const float* __restrict__ in, float* __restrict__ out) {
    __shared__ float tile[32][36];
    int b = blockIdx.z;
    int l0 = blockIdx.x * 32, h0 = blockIdx.y * 32;
    int t = threadIdx.x;                 // 256
    {
        int hh = t >> 3, lq = t & 7;
        float4 v = *(const float4*)(in + ((size_t)b * H_ + h0 + hh) * L_ + l0 + lq * 4);
        tile[lq * 4 + 0][hh] = v.x;
        tile[lq * 4 + 1][hh] = v.y;
        tile[lq * 4 + 2][hh] = v.z;
        tile[lq * 4 + 3][hh] = v.w;
    }
    __syncthreads();
    {
        int l = t >> 3, hq = t & 7;
        float4 w = *(const float4*)&tile[l][hq * 4];
        *(float4*)(out + ((size_t)b * L_ + l0 + l) * H_ + h0 + hq * 4) = w;
    }
}

// ---------------- u staging: fp32 -> fp16 padded tile -------------------------
__device__ __forceinline__ void stage_u1(char* smc, const float* __restrict__ up,
                                         int buf, int tid) {
    float4 v = ((const float4*)up)[tid];
    __half* uh = (__half*)(smc + oU + buf * 4608);
    int idx = (tid >> 4) * 72 + (tid & 15) * 4;
    __half2 p0; p0.x = __float2half_rn(v.x); p0.y = __float2half_rn(v.y);
    __half2 p1; p1.x = __float2half_rn(v.z); p1.y = __float2half_rn(v.w);
    *(__half2*)(uh + idx)     = p0;
    *(__half2*)(uh + idx + 2) = p1;
}

// ---------------- fused HMMA kernel: fp16 single-pass, k-major X (80B rows) ---
extern __shared__ char smc[];
__global__ __launch_bounds__(512, 1) void fused_kernel() {
    int h   = blockIdx.y;
    int b0  = blockIdx.x * 8;
    int tid = threadIdx.x;
    int w   = tid >> 5, lane = tid & 31;

    uint32_t sb = smem_to_u32(smc);

    // ---- stage operators: W 18432 B + A2 27648 B
    {
        const float4* s = (const float4*)(gW + (size_t)h * 9216);
        float4* d = (float4*)(smc + oWH);
        for (int i = tid; i < 1152; i += 512) d[i] = s[i];
        s = (const float4*)(gA2 + (size_t)h * 13824);
        d = (float4*)(smc + oA2);
        for (int i = tid; i < 1728; i += 512) d[i] = s[i];
    }
    stage_u1(smc, d_ut + ((size_t)b0 * H_ + h) * L_, 0, tid);
    stage_u1(smc, d_ut + ((size_t)(b0 + 1) * H_ + h) * L_, 1, tid);

    // scan constants: n = tid>>3, q = tid&7
    int sn = tid >> 3, sq = tid & 7;
    float2 a1  = d_AbC[h * 64 + sn];
    float2 a2c = cmul(a1, a1);
    float2 a3c = cmul(a2c, a1);
    float2 a4c = cmul(a2c, a2c);
    float2 a8c = cmul(a4c, a4c);
    float2 a16c = cmul(a8c, a8c);
    __syncthreads();

    uint32_t laneA  = (uint32_t)(((lane & 15) * 72 + (lane >> 4) * 8) * 2);
    uint32_t laneB  = (uint32_t)(((lane & 7) * 72 + ((lane >> 3) & 1) * 8) * 2);
    uint32_t laneBT = (uint32_t)((lane & 15) * 80);   // k-major rows (80B, 16B-aligned)

    // MMA1 tiling: mq1 = 16-row m-tile, nh1 = 16-col n-half; W frags cached
    int mq1 = w & 7, nh1 = w >> 3;
    uint32_t w1A[4][4];
    {
        uint32_t w1Hb = sb + oWH + (uint32_t)(mq1 * 16 * 144) + laneA;
        #pragma unroll
        for (int kt = 0; kt < 4; kt++) ldm_x4(w1A[kt], w1Hb + (uint32_t)(kt * 32));
    }

    // MMA2 tiling: mq2 m-tile, nh2 n-half, ng k-half (6 k-chunks each); cached
    int mq2 = w & 3, nh2 = (w >> 2) & 1, ng = w >> 3;
    uint32_t a2A[6][4];
    #pragma unroll
    for (int kcl = 0; kcl < 6; kcl++) {
        int kc = ng * 6 + kcl, sg = kc >> 2, kt = kc & 3;
        uint32_t base = sb + oA2 + (uint32_t)(sg * 9216 + mq2 * 16 * 144 + kt * 32) + laneA;
        ldm_x4(a2A[kcl], base);
    }

    float* sD1f = (float*)(smc + oD1);
    int gid = lane >> 2, tq = lane & 3;

    for (int it = 0; it < 4; it++) {
        int bb0 = (2 * it) & 3, bb1 = (2 * it + 1) & 3;

        // ======== P1: MMA1 both batches (single fp16 pass) ========
        {
            uint32_t uh0 = sb + oU + (uint32_t)(bb0 * 4608) + laneB;
            uint32_t uh1 = sb + oU + (uint32_t)(bb1 * 4608) + laneB;
            float acc[2][2][4];
            #pragma unroll
            for (int bt = 0; bt < 2; bt++)
                #pragma unroll
                for (int nt = 0; nt < 2; nt++)
                    #pragma unroll
                    for (int i = 0; i < 4; i++) acc[bt][nt][i] = 0.f;
            #pragma unroll
            for (int kt = 0; kt < 4; kt++) {
                uint32_t ko = kt * 32;
                #pragma unroll
                for (int nt = 0; nt < 2; nt++) {
                    uint32_t bo = (uint32_t)((nh1 * 2 + nt) * 1152) + ko;
                    uint32_t bh[2];
                    ldm_x2(bh, uh0 + bo);
                    mma16816h(acc[0][nt], w1A[kt], bh);
                    ldm_x2(bh, uh1 + bo);
                    mma16816h(acc[1][nt], w1A[kt], bh);
                }
            }
            #pragma unroll
            for (int bt = 0; bt < 2; bt++)
                #pragma unroll
                for (int nt = 0; nt < 2; nt++) {
                    int c0 = nh1 * 16 + nt * 8 + tq * 2;
                    int r0 = mq1 * 16 + gid;
                    float* D1b = sD1f + bt * 4608;
                    D1b[r0 * 36 + c0]           = acc[bt][nt][0];
                    D1b[r0 * 36 + c0 + 1]       = acc[bt][nt][1];
                    D1b[(r0 + 8) * 36 + c0]     = acc[bt][nt][2];
                    D1b[(r0 + 8) * 36 + c0 + 1] = acc[bt][nt][3];
                }
        }
        __syncthreads();

        // ======== P2: scan both batches + emit k-major X; stage next u ========
        #pragma unroll
        for (int bt = 0; bt < 2; bt++) {
            float* D1b = sD1f + bt * 4608;
            __half* Xt = (__half*)(smc + oX + bt * 10240);   // [128 k][40 c]

            float4 gr4 = *(const float4*)(D1b + sn * 36 + sq * 4);
            float4 gi4 = *(const float4*)(D1b + (64 + sn) * 36 + sq * 4);
            float h0r = gr4.x, h0i = gi4.x;
            float h1r = a1.x * h0r - a1.y * h0i + gr4.y;
            float h1i = a1.x * h0i + a1.y * h0r + gi4.y;
            float h2r = a1.x * h1r - a1.y * h1i + gr4.z;
            float h2i = a1.x * h1i + a1.y * h1r + gi4.z;
            float Sr  = a1.x * h2r - a1.y * h2i + gr4.w;
            float Si  = a1.x * h2i + a1.y * h2r + gi4.w;
            float tr, ti;
            tr = __shfl_up_sync(0xffffffffu, Sr, 1, 8);
            ti = __shfl_up_sync(0xffffffffu, Si, 1, 8);
            if (sq >= 1) { Sr += a4c.x * tr - a4c.y * ti;  Si += a4c.x * ti + a4c.y * tr; }
            tr = __shfl_up_sync(0xffffffffu, Sr, 2, 8);
            ti = __shfl_up_sync(0xffffffffu, Si, 2, 8);
            if (sq >= 2) { Sr += a8c.x * tr - a8c.y * ti;  Si += a8c.x * ti + a8c.y * tr; }
            tr = __shfl_up_sync(0xffffffffu, Sr, 4, 8);
            ti = __shfl_up_sync(0xffffffffu, Si, 4, 8);
            if (sq >= 4) { Sr += a16c.x * tr - a16c.y * ti; Si += a16c.x * ti + a16c.y * tr; }
            float X0r = __shfl_up_sync(0xffffffffu, Sr, 1, 8);
            float X0i = __shfl_up_sync(0xffffffffu, Si, 1, 8);
            if (sq == 0) { X0r = 0.f; X0i = 0.f; }

            float v1r = a1.x * X0r - a1.y * X0i + h0r;
            float v1i = a1.x * X0i + a1.y * X0r + h0i;
            float v2r = a2c.x * X0r - a2c.y * X0i + h1r;
            float v2i = a2c.x * X0i + a2c.y * X0r + h1i;
            float v3r = a3c.x * X0r - a3c.y * X0i + h2r;
            float v3i = a3c.x * X0i + a3c.y * X0r + h2i;

            __half2 r01, r23, i01, i23;
            r01.x = __float2half_rn(X0r);  r01.y = __float2half_rn(v1r);
            r23.x = __float2half_rn(v2r);  r23.y = __float2half_rn(v3r);
            i01.x = __float2half_rn(X0i);  i01.y = __float2half_rn(v1i);
            i23.x = __float2half_rn(v2i);  i23.y = __float2half_rn(v3i);
            uint2 pk;
            pk.x = *(uint32_t*)&r01;  pk.y = *(uint32_t*)&r23;
            *(uint2*)(Xt + sn * 40 + sq * 4) = pk;          // xr row sn
            pk.x = *(uint32_t*)&i01;  pk.y = *(uint32_t*)&i23;
            *(uint2*)(Xt + (64 + sn) * 40 + sq * 4) = pk;   // xi row 64+sn
        }
        if (it < 3) {
            stage_u1(smc, d_ut + ((size_t)(b0 + 2 * it + 2) * H_ + h) * L_, (2 * it + 2) & 3, tid);
            stage_u1(smc, d_ut + ((size_t)(b0 + 2 * it + 3) * H_ + h) * L_, (2 * it + 3) & 3, tid);
        }
        __syncthreads();

        // ======== P3: MMA2 both batches (trans B for x segs; D2 overlays D1) ==
        #pragma unroll
        for (int bt = 0; bt < 2; bt++) {
            uint32_t uhBp = sb + oU + (uint32_t)(((2 * it + bt) & 3) * 4608) + laneB;
            uint32_t xBase = sb + oX + (uint32_t)(bt * 10240) + laneBT;
            float acc[2][4];
            #pragma unroll
            for (int nt = 0; nt < 2; nt++)
                #pragma unroll
                for (int i = 0; i < 4; i++) acc[nt][i] = 0.f;
            #pragma unroll
            for (int kcl = 0; kcl < 6; kcl++) {
                int kc = ng * 6 + kcl, sg = kc >> 2, kt = kc & 3;
                if (sg == 2) {
                    uint32_t bHB = uhBp + (uint32_t)(kt * 32);
                    #pragma unroll
                    for (int nt = 0; nt < 2; nt++) {
                        uint32_t bh[2];
                        ldm_x2(bh, bHB + (uint32_t)((nh2 * 2 + nt) * 1152));
                        mma16816h(acc[nt], a2A[kcl], bh);
                    }
                } else {
                    uint32_t bHB = xBase + (uint32_t)((sg * 64 + kt * 16) * 80);
                    #pragma unroll
                    for (int nt = 0; nt < 2; nt++) {
                        uint32_t bh[2];
                        ldm_x2t(bh, bHB + (uint32_t)(nh2 * 32 + nt * 16));
                        mma16816h(acc[nt], a2A[kcl], bh);
                    }
                }
            }
            float* sD2 = sD1f + (bt * 2 + ng) * 2112;
            #pragma unroll
            for (int nt = 0; nt < 2; nt++) {
                int c0 = nh2 * 16 + nt * 8 + tq * 2;
                int i0 = mq2 * 16 + gid;
                sD2[i0 * 33 + c0]           = acc[nt][0];
                sD2[i0 * 33 + c0 + 1]       = acc[nt][1];
                sD2[(i0 + 8) * 33 + c0]     = acc[nt][2];
                sD2[(i0 + 8) * 33 + c0 + 1] = acc[nt][3];
            }
        }
        __syncthreads();

        // ======== P4: store y both batches ========
        {
            int bt = tid >> 8, t = tid & 255;
            float* sD2a = sD1f + bt * 2 * 2112;
            float* yp = d_yt + ((size_t)(b0 + 2 * it + bt) * H_ + h) * L_;
            #pragma unroll
            for (int rep = 0; rep < 2; rep++) {
                int idx = rep * 256 + t;
                int c = idx >> 4, i0 = (idx & 15) * 4;
                float4 y4;
                y4.x = sD2a[(i0 + 0) * 33 + c] + sD2a[2112 + (i0 + 0) * 33 + c];
                y4.y = sD2a[(i0 + 1) * 33 + c] + sD2a[2112 + (i0 + 1) * 33 + c];
                y4.z = sD2a[(i0 + 2) * 33 + c] + sD2a[2112 + (i0 + 2) * 33 + c];
                y4.w = sD2a[(i0 + 3) * 33 + c] + sD2a[2112 + (i0 + 3) * 33 + c];
                *(float4*)(yp + c * 64 + i0) = y4;
            }
        }
        __syncthreads();
    }
}

// ---------------- launch --------------------------------------------------------
extern "C" void kernel_launch(void* const* d_in, const int* in_sizes, int n_in,
                              void* d_out, int out_size) {
    const float* u     = (const float*)d_in[0];
    const float* Lr    = (const float*)d_in[1];
    const float* Li    = (const float*)d_in[2];
    const float* Br    = (const float*)d_in[3];
    const float* Bi    = (const float*)d_in[4];
    const float* Cr    = (const float*)d_in[5];
    const float* Ci    = (const float*)d_in[6];
    const float* logdt = (const float*)d_in[7];
    const float* D     = (const float*)d_in[8];
    float* out = (float*)d_out;

    float* ut_ptr; cudaGetSymbolAddress((void**)&ut_ptr, d_ut);
    float* yt_ptr; cudaGetSymbolAddress((void**)&yt_ptr, d_yt);

    cudaFuncSetAttribute(fused_kernel, cudaFuncAttributeMaxDynamicSharedMemorySize, SMEM_TOTAL);

    precompute_kernel<<<H_ / 2, N_>>>(Lr, Li, Br, Bi, Cr, Ci, logdt, D, 0);
    precompute_kernel<<<H_ / 2, N_>>>(Lr, Li, Br, Bi, Cr, Ci, logdt, D, H_ / 2);
    transpose_BLH_to_BHL<<<dim3(H_ / 32, L_ / 32, B_), 256>>>(u, ut_ptr);
    fused_kernel<<<dim3(2, H_), 512, SMEM_TOTAL>>>();
    transpose_BHL_to_BLH<<<dim3(L_ / 32, H_ / 32, B_), 256>>>(yt_ptr, out);
}